// round 2
// baseline (speedup 1.0000x reference)
#include <cuda_runtime.h>
#include <math.h>

// Problem constants
#define BATCH 128
#define HDIM  512
#define IDIM  512
#define NG    (6 * HDIM)   // 3072 gate columns
#define INV_SQRT_H 0.04419417382415922f  // 1/sqrt(512)

// Output layout: concat(h_t [B,H], C_t [B,H,H], m_t [B,H], n_t [B,H])
#define OUT_H 0
#define OUT_C (BATCH * HDIM)                                // 65536
#define OUT_M (OUT_C + (long)BATCH * HDIM * HDIM)           // 33619968
#define OUT_N (OUT_M + BATCH * HDIM)                        // 33685504

// Scratch (device globals — no allocation allowed)
__device__ float g_gates[BATCH * NG];
__device__ float g_f[BATCH * HDIM];
__device__ float g_add[BATCH * HDIM];
__device__ float g_o[BATCH * HDIM];
__device__ float g_Cq[BATCH * HDIM];
__device__ float g_sumq[BATCH];
__device__ float g_invden[BATCH];

// ---------------------------------------------------------------------------
// K1: gates = x @ W^T + b     (M=128, N=3072, K=512; both operands K-contiguous)
// 64x64 block tile, BK=16, 256 threads, 4x4 per thread.
// ---------------------------------------------------------------------------
__global__ __launch_bounds__(256) void gemm_gates_kernel(
    const float* __restrict__ A,    // x    [128,512]
    const float* __restrict__ Wm,   // W    [3072,512]
    const float* __restrict__ bias) // b    [3072]
{
    const int BM = 64, BN = 64, BK = 16;
    __shared__ float sA[BK][BM];
    __shared__ float sB[BK][BN];

    int tid = threadIdx.x;
    int m0 = blockIdx.y * BM;
    int n0 = blockIdx.x * BN;
    int tx = tid & 15;    // 16 col-groups
    int ty = tid >> 4;    // 16 row-groups

    float acc[4][4];
#pragma unroll
    for (int i = 0; i < 4; i++)
#pragma unroll
        for (int j = 0; j < 4; j++) acc[i][j] = 0.f;

    int lr = tid >> 2;        // 0..63 : tile row
    int lc = (tid & 3) * 4;   // 0,4,8,12 : k offset

    for (int k0 = 0; k0 < IDIM; k0 += BK) {
        float4 va = *reinterpret_cast<const float4*>(A  + (long)(m0 + lr) * IDIM + k0 + lc);
        float4 vb = *reinterpret_cast<const float4*>(Wm + (long)(n0 + lr) * IDIM + k0 + lc);
        sA[lc + 0][lr] = va.x; sA[lc + 1][lr] = va.y;
        sA[lc + 2][lr] = va.z; sA[lc + 3][lr] = va.w;
        sB[lc + 0][lr] = vb.x; sB[lc + 1][lr] = vb.y;
        sB[lc + 2][lr] = vb.z; sB[lc + 3][lr] = vb.w;
        __syncthreads();

#pragma unroll
        for (int k = 0; k < BK; k++) {
            float a[4], bq[4];
#pragma unroll
            for (int i = 0; i < 4; i++) a[i] = sA[k][ty * 4 + i];
#pragma unroll
            for (int j = 0; j < 4; j++) bq[j] = sB[k][tx * 4 + j];
#pragma unroll
            for (int i = 0; i < 4; i++)
#pragma unroll
                for (int j = 0; j < 4; j++) acc[i][j] += a[i] * bq[j];
        }
        __syncthreads();
    }

#pragma unroll
    for (int i = 0; i < 4; i++) {
        int m = m0 + ty * 4 + i;
#pragma unroll
        for (int j = 0; j < 4; j++) {
            int n = n0 + tx * 4 + j;
            g_gates[(long)m * NG + n] = acc[i][j] + bias[n];
        }
    }
}

// ---------------------------------------------------------------------------
// K2: elementwise gate math over [B,H]: m_t, n_t (to out), f_t, add, o_t (scratch)
// ---------------------------------------------------------------------------
__global__ __launch_bounds__(256) void gate_kernel(
    const float* __restrict__ m_prev,
    const float* __restrict__ n_prev,
    float* __restrict__ out)
{
    int idx = blockIdx.x * blockDim.x + threadIdx.x;   // 0..65535
    int b = idx >> 9;
    int h = idx & (HDIM - 1);
    const float* g = g_gates + (long)b * NG;

    float ig = g[h];
    float fg = g[HDIM + h];
    float og = g[2 * HDIM + h];
    float kg = g[4 * HDIM + h];
    float vg = g[5 * HDIM + h];

    float mp = m_prev[idx];
    float mt = fmaxf(fg + mp, ig);
    float it = expf(ig - mt);
    float ft = expf(fg + mp - mt);
    float kt = INV_SQRT_H * kg;
    float nt = ft * n_prev[idx] + it * kt;

    out[OUT_M + idx] = mt;
    out[OUT_N + idx] = nt;
    g_f[idx]   = ft;
    g_add[idx] = it * vg * kt;
    g_o[idx]   = 1.f / (1.f + expf(-og));
}

// ---------------------------------------------------------------------------
// K3: per-batch reductions — sum(q) and nq = dot(n_t, q); one block per b.
// Deterministic tree reduction (no atomics).
// ---------------------------------------------------------------------------
__global__ __launch_bounds__(256) void reduce_kernel(const float* __restrict__ out)
{
    int b = blockIdx.x;
    const float* q  = g_gates + (long)b * NG + 3 * HDIM;
    const float* nt = out + OUT_N + (long)b * HDIM;

    float sq = 0.f, nq = 0.f;
    for (int h = threadIdx.x; h < HDIM; h += 256) {
        float qv = q[h];
        sq += qv;
        nq += nt[h] * qv;
    }
    // warp reduce
    for (int s = 16; s; s >>= 1) {
        sq += __shfl_xor_sync(0xffffffffu, sq, s);
        nq += __shfl_xor_sync(0xffffffffu, nq, s);
    }
    __shared__ float s1[8], s2[8];
    int warp = threadIdx.x >> 5, lane = threadIdx.x & 31;
    if (lane == 0) { s1[warp] = sq; s2[warp] = nq; }
    __syncthreads();
    if (warp == 0) {
        sq = (lane < 8) ? s1[lane] : 0.f;
        nq = (lane < 8) ? s2[lane] : 0.f;
        for (int s = 4; s; s >>= 1) {
            sq += __shfl_xor_sync(0xffffffffu, sq, s);
            nq += __shfl_xor_sync(0xffffffffu, nq, s);
        }
        if (lane == 0) {
            g_sumq[b]   = sq;
            g_invden[b] = 1.f / fmaxf(fabsf(nq), 1e-6f);
        }
    }
}

// ---------------------------------------------------------------------------
// K4: THE bandwidth kernel. One warp per C row (2KB): C_t = f*C_prev + add,
// fused Cq = f*dot(C_prev_row, q) + add*sum_q. 256 threads = 8 rows/block,
// all rows in a block share batch b -> q cached once in smem.
// ---------------------------------------------------------------------------
__global__ __launch_bounds__(256) void stream_C_kernel(
    const float* __restrict__ Cprev,
    float* __restrict__ out)
{
    __shared__ float sq[HDIM];
    int b  = blockIdx.x >> 6;     // 64 blocks per batch (512 rows / 8)
    int rg = blockIdx.x & 63;
    int tid = threadIdx.x;

    // load q[b,:] (512 floats) via float2 x 256 threads
    const float* qrow = g_gates + (long)b * NG + 3 * HDIM;
    reinterpret_cast<float2*>(sq)[tid] = reinterpret_cast<const float2*>(qrow)[tid];
    __syncthreads();

    int warp = tid >> 5, lane = tid & 31;
    int i = rg * 8 + warp;
    int bh = b * HDIM + i;
    long rowoff = ((long)b * HDIM + i) * HDIM;

    float fv = g_f[bh];
    float av = g_add[bh];

    const float4* src = reinterpret_cast<const float4*>(Cprev + rowoff);
    float4*       dst = reinterpret_cast<float4*>(out + OUT_C + rowoff);
    const float4* qsv = reinterpret_cast<const float4*>(sq);

    float dot = 0.f;
#pragma unroll
    for (int u = 0; u < 4; u++) {
        int idx = lane + u * 32;          // 128 float4 per row
        float4 c  = src[idx];
        float4 qv = qsv[idx];
        dot += c.x * qv.x + c.y * qv.y + c.z * qv.z + c.w * qv.w;
        float4 o;
        o.x = fv * c.x + av;
        o.y = fv * c.y + av;
        o.z = fv * c.z + av;
        o.w = fv * c.w + av;
        dst[idx] = o;
    }
    for (int s = 16; s; s >>= 1) dot += __shfl_xor_sync(0xffffffffu, dot, s);
    if (lane == 0) g_Cq[bh] = fv * dot + av * g_sumq[b];
}

// ---------------------------------------------------------------------------
// K5: h_t = o_t * Cq * invden[b]
// ---------------------------------------------------------------------------
__global__ __launch_bounds__(256) void hout_kernel(float* __restrict__ out)
{
    int idx = blockIdx.x * blockDim.x + threadIdx.x;
    int b = idx >> 9;
    out[OUT_H + idx] = g_o[idx] * g_Cq[idx] * g_invden[b];
}

// ---------------------------------------------------------------------------
// Launch. Inputs (metadata order): x, h_prev, C_prev, m_prev, n_prev, W, b
// ---------------------------------------------------------------------------
extern "C" void kernel_launch(void* const* d_in, const int* in_sizes, int n_in,
                              void* d_out, int out_size)
{
    const float* x      = (const float*)d_in[0];
    // d_in[1] = h_prev (unused by reference)
    const float* C_prev = (const float*)d_in[2];
    const float* m_prev = (const float*)d_in[3];
    const float* n_prev = (const float*)d_in[4];
    const float* W      = (const float*)d_in[5];
    const float* bias   = (const float*)d_in[6];
    float* out = (float*)d_out;

    // K1: GEMM gates
    dim3 ggrid(NG / 64, BATCH / 64);
    gemm_gates_kernel<<<ggrid, 256>>>(x, W, bias);

    // K2: gate elementwise
    gate_kernel<<<(BATCH * HDIM) / 256, 256>>>(m_prev, n_prev, out);

    // K3: per-batch reductions
    reduce_kernel<<<BATCH, 256>>>(out);

    // K4: C stream + fused Cq
    stream_C_kernel<<<BATCH * (HDIM / 8), 256>>>(C_prev, out);

    // K5: h_t
    hout_kernel<<<(BATCH * HDIM) / 256, 256>>>(out);
}

// round 4
// speedup vs baseline: 1.1404x; 1.1404x over previous
#include <cuda_runtime.h>
#include <math.h>

// Problem constants
#define BATCH 128
#define HDIM  512
#define IDIM  512
#define NG    (6 * HDIM)   // 3072 gate columns
#define INV_SQRT_H 0.04419417382415922f  // 1/sqrt(512)

// Output layout: concat(h_t [B,H], C_t [B,H,H], m_t [B,H], n_t [B,H])
#define OUT_H 0
#define OUT_C (BATCH * HDIM)                                // 65536
#define OUT_M (OUT_C + (long)BATCH * HDIM * HDIM)           // 33619968
#define OUT_N (OUT_M + BATCH * HDIM)                        // 33685504

// Scratch (device globals — no allocation allowed)
__device__ float g_gates[BATCH * NG];
__device__ float g_f[BATCH * HDIM];
__device__ float g_add[BATCH * HDIM];
__device__ float g_o[BATCH * HDIM];
__device__ float g_sumq[BATCH];
__device__ float g_invden[BATCH];

// ---------------------------------------------------------------------------
// K1: gates = x @ W^T + b   (M=128, N=3072, K=512; both K-contiguous)
// BM=32, BN=64, BK=16, 128 threads, 4x4 per thread -> 192 blocks, small
// footprint so many blocks co-reside per SM (fixes the 25%-occupancy stall
// of the previous 96-block version).
// ---------------------------------------------------------------------------
#define GBM 32
#define GBN 64
#define GBK 16

__global__ __launch_bounds__(128) void gemm_gates_kernel(
    const float* __restrict__ A,    // x [128,512]
    const float* __restrict__ Wm,   // W [3072,512]
    const float* __restrict__ bias) // b [3072]
{
    __shared__ float sA[GBK][GBM];
    __shared__ float sB[GBK][GBN];

    int tid = threadIdx.x;
    int m0 = blockIdx.y * GBM;
    int n0 = blockIdx.x * GBN;
    int tx = tid & 15;    // 16 col-groups -> 64 cols
    int ty = tid >> 4;    // 8  row-groups -> 32 rows

    float acc[4][4];
#pragma unroll
    for (int i = 0; i < 4; i++)
#pragma unroll
        for (int j = 0; j < 4; j++) acc[i][j] = 0.f;

    int lr = tid >> 2;        // 0..31 : row within tile
    int lc = (tid & 3) * 4;   // 0,4,8,12 : k offset (float4)

    for (int k0 = 0; k0 < IDIM; k0 += GBK) {
        // A tile: 32 rows x 16 k -> one float4 per thread
        float4 va = *reinterpret_cast<const float4*>(A + (long)(m0 + lr) * IDIM + k0 + lc);
        sA[lc + 0][lr] = va.x; sA[lc + 1][lr] = va.y;
        sA[lc + 2][lr] = va.z; sA[lc + 3][lr] = va.w;
        // B tile: 64 rows x 16 k -> two float4 per thread
        float4 vb0 = *reinterpret_cast<const float4*>(Wm + (long)(n0 + lr) * IDIM + k0 + lc);
        float4 vb1 = *reinterpret_cast<const float4*>(Wm + (long)(n0 + 32 + lr) * IDIM + k0 + lc);
        sB[lc + 0][lr] = vb0.x; sB[lc + 1][lr] = vb0.y;
        sB[lc + 2][lr] = vb0.z; sB[lc + 3][lr] = vb0.w;
        sB[lc + 0][32 + lr] = vb1.x; sB[lc + 1][32 + lr] = vb1.y;
        sB[lc + 2][32 + lr] = vb1.z; sB[lc + 3][32 + lr] = vb1.w;
        __syncthreads();

#pragma unroll
        for (int k = 0; k < GBK; k++) {
            float a[4], bq[4];
#pragma unroll
            for (int i = 0; i < 4; i++) a[i] = sA[k][ty * 4 + i];
#pragma unroll
            for (int j = 0; j < 4; j++) bq[j] = sB[k][tx * 4 + j];
#pragma unroll
            for (int i = 0; i < 4; i++)
#pragma unroll
                for (int j = 0; j < 4; j++) acc[i][j] += a[i] * bq[j];
        }
        __syncthreads();
    }

#pragma unroll
    for (int i = 0; i < 4; i++) {
        int m = m0 + ty * 4 + i;
#pragma unroll
        for (int j = 0; j < 4; j++) {
            int n = n0 + tx * 4 + j;
            g_gates[(long)m * NG + n] = acc[i][j] + bias[n];
        }
    }
}

// ---------------------------------------------------------------------------
// K2: fused gate elementwise + per-batch reductions. One block (512 thr) per
// batch: compute m_t, n_t, f, add, o; then block-reduce sum(q) and nq=dot(n,q).
// ---------------------------------------------------------------------------
__global__ __launch_bounds__(512) void gatered_kernel(
    const float* __restrict__ m_prev,
    const float* __restrict__ n_prev,
    float* __restrict__ out)
{
    int b = blockIdx.x;
    int h = threadIdx.x;           // 0..511
    int idx = b * HDIM + h;
    const float* g = g_gates + (long)b * NG;

    float ig = g[h];
    float fg = g[HDIM + h];
    float og = g[2 * HDIM + h];
    float qv = g[3 * HDIM + h];
    float kg = g[4 * HDIM + h];
    float vg = g[5 * HDIM + h];

    float mp = m_prev[idx];
    float mt = fmaxf(fg + mp, ig);
    float it = expf(ig - mt);
    float ft = expf(fg + mp - mt);
    float kt = INV_SQRT_H * kg;
    float nt = ft * n_prev[idx] + it * kt;

    out[OUT_M + idx] = mt;
    out[OUT_N + idx] = nt;
    g_f[idx]   = ft;
    g_add[idx] = it * vg * kt;
    g_o[idx]   = 1.f / (1.f + expf(-og));

    // block reductions: sq = sum(q), nq = dot(n_t, q)
    float sq = qv;
    float nq = nt * qv;
    for (int s = 16; s; s >>= 1) {
        sq += __shfl_xor_sync(0xffffffffu, sq, s);
        nq += __shfl_xor_sync(0xffffffffu, nq, s);
    }
    __shared__ float s1[16], s2[16];
    int warp = h >> 5, lane = h & 31;
    if (lane == 0) { s1[warp] = sq; s2[warp] = nq; }
    __syncthreads();
    if (warp == 0) {
        sq = (lane < 16) ? s1[lane] : 0.f;
        nq = (lane < 16) ? s2[lane] : 0.f;
        for (int s = 8; s; s >>= 1) {
            sq += __shfl_xor_sync(0xffffffffu, sq, s);
            nq += __shfl_xor_sync(0xffffffffu, nq, s);
        }
        if (lane == 0) {
            g_sumq[b]   = sq;
            g_invden[b] = 1.f / fmaxf(fabsf(nq), 1e-6f);
        }
    }
}

// ---------------------------------------------------------------------------
// K3: THE bandwidth kernel. One warp per C row (2KB): C_t = f*C_prev + add,
// fused Cq = f*dot(C_prev_row, q) + add*sum_q, and h_t written directly.
// Streaming cache hints: C has zero reuse.
// ---------------------------------------------------------------------------
__global__ __launch_bounds__(256) void stream_C_kernel(
    const float* __restrict__ Cprev,
    float* __restrict__ out)
{
    __shared__ float sq[HDIM];
    int b  = blockIdx.x >> 6;     // 64 blocks per batch (512 rows / 8)
    int rg = blockIdx.x & 63;
    int tid = threadIdx.x;

    // load q[b,:] into smem (float2 x 256 threads)
    const float* qrow = g_gates + (long)b * NG + 3 * HDIM;
    reinterpret_cast<float2*>(sq)[tid] = reinterpret_cast<const float2*>(qrow)[tid];
    __syncthreads();

    int warp = tid >> 5, lane = tid & 31;
    int i = rg * 8 + warp;
    int bh = b * HDIM + i;
    long rowoff = ((long)b * HDIM + i) * HDIM;

    float fv = g_f[bh];
    float av = g_add[bh];

    const float4* src = reinterpret_cast<const float4*>(Cprev + rowoff);
    float4*       dst = reinterpret_cast<float4*>(out + OUT_C + rowoff);
    const float4* qsv = reinterpret_cast<const float4*>(sq);

    // batch all 4 independent 16B loads first (MLP), then compute+store
    float4 c[4], qv[4];
#pragma unroll
    for (int u = 0; u < 4; u++) c[u] = __ldcs(&src[lane + u * 32]);
#pragma unroll
    for (int u = 0; u < 4; u++) qv[u] = qsv[lane + u * 32];

    float dot = 0.f;
#pragma unroll
    for (int u = 0; u < 4; u++) {
        dot += c[u].x * qv[u].x + c[u].y * qv[u].y
             + c[u].z * qv[u].z + c[u].w * qv[u].w;
        float4 o;
        o.x = fv * c[u].x + av;
        o.y = fv * c[u].y + av;
        o.z = fv * c[u].z + av;
        o.w = fv * c[u].w + av;
        __stcs(&dst[lane + u * 32], o);
    }
    for (int s = 16; s; s >>= 1) dot += __shfl_xor_sync(0xffffffffu, dot, s);
    if (lane == 0) {
        float cq = fv * dot + av * g_sumq[b];
        out[OUT_H + bh] = g_o[bh] * cq * g_invden[b];
    }
}

// ---------------------------------------------------------------------------
// Launch. Inputs (metadata order): x, h_prev, C_prev, m_prev, n_prev, W, b
// ---------------------------------------------------------------------------
extern "C" void kernel_launch(void* const* d_in, const int* in_sizes, int n_in,
                              void* d_out, int out_size)
{
    const float* x      = (const float*)d_in[0];
    // d_in[1] = h_prev (unused by reference)
    const float* C_prev = (const float*)d_in[2];
    const float* m_prev = (const float*)d_in[3];
    const float* n_prev = (const float*)d_in[4];
    const float* W      = (const float*)d_in[5];
    const float* bias   = (const float*)d_in[6];
    float* out = (float*)d_out;

    // K1: GEMM gates  (192 blocks x 128 threads)
    dim3 ggrid(NG / GBN, BATCH / GBM);
    gemm_gates_kernel<<<ggrid, 128>>>(x, W, bias);

    // K2: fused gate elementwise + reductions
    gatered_kernel<<<BATCH, 512>>>(m_prev, n_prev, out);

    // K3: C stream + fused Cq + h_t
    stream_C_kernel<<<BATCH * (HDIM / 8), 256>>>(C_prev, out);
}

// round 6
// speedup vs baseline: 1.2336x; 1.0817x over previous
#include <cuda_runtime.h>
#include <math.h>

// Problem constants
#define BATCH 128
#define HDIM  512
#define IDIM  512
#define NG    (6 * HDIM)   // 3072 gate columns
#define INV_SQRT_H 0.04419417382415922f  // 1/sqrt(512)

// Output layout: concat(h_t [B,H], C_t [B,H,H], m_t [B,H], n_t [B,H])
#define OUT_H 0
#define OUT_C (BATCH * HDIM)                                // 65536
#define OUT_M (OUT_C + (long)BATCH * HDIM * HDIM)           // 33619968
#define OUT_N (OUT_M + BATCH * HDIM)                        // 33685504

// Scratch (device globals — no allocation allowed)
__device__ float g_part[2][BATCH * NG];  // split-K partial gate sums
__device__ float g_q[BATCH * HDIM];      // biased q (for stream kernel)
__device__ float g_f[BATCH * HDIM];
__device__ float g_add[BATCH * HDIM];
__device__ float g_o[BATCH * HDIM];
__device__ float g_sumq[BATCH];
__device__ float g_invden[BATCH];

// ---------------------------------------------------------------------------
// K1: partial gates = x @ W^T over half the K range (split-K = 2).
// fp32 FFMA (accuracy-critical: reduced-precision formats fail the 1e-3
// threshold via the nq-denominator amplification).
// BM=32, BN=64, BK=16, 256 threads, 2x4 per thread.
// grid (48, 4, 2) = 384 blocks -> ~2.6 blocks/SM, ~20 warps/SM.
// ---------------------------------------------------------------------------
#define SBM 32
#define SBN 64
#define SBK 16
#define KSPLIT 256   // IDIM / 2

__global__ __launch_bounds__(256) void gemm_splitk_kernel(
    const float* __restrict__ x,    // [128,512]
    const float* __restrict__ Wm)   // [3072,512]
{
    __shared__ float sA[SBK][SBM + 1];  // +1 pad: kill store bank conflicts
    __shared__ float sB[SBK][SBN];      // unpadded: float4 reads stay aligned

    int tid = threadIdx.x;
    int n0 = blockIdx.x * SBN;
    int m0 = blockIdx.y * SBM;
    int kbase = blockIdx.z * KSPLIT;
    float* dst = &g_part[blockIdx.z][0];

    int tx = tid & 15;     // 16 col-groups * 4 = 64 cols
    int ty = tid >> 4;     // 16 row-groups * 2 = 32 rows

    int alr = tid >> 3, alc = (tid & 7) * 2;  // A: row 0..31, k-off {0,2,..,14}
    int blr = tid >> 2, blc = (tid & 3) * 4;  // B: row 0..63, k-off {0,4,8,12}

    float acc[2][4];
#pragma unroll
    for (int i = 0; i < 2; i++)
#pragma unroll
        for (int j = 0; j < 4; j++) acc[i][j] = 0.f;

    // prefetch first tile
    float2 va = *reinterpret_cast<const float2*>(x  + (long)(m0 + alr) * IDIM + kbase + alc);
    float4 vb = *reinterpret_cast<const float4*>(Wm + (long)(n0 + blr) * IDIM + kbase + blc);

    for (int kt = 0; kt < KSPLIT; kt += SBK) {
        sA[alc + 0][alr] = va.x; sA[alc + 1][alr] = va.y;
        sB[blc + 0][blr] = vb.x; sB[blc + 1][blr] = vb.y;
        sB[blc + 2][blr] = vb.z; sB[blc + 3][blr] = vb.w;
        __syncthreads();

        if (kt + SBK < KSPLIT) {  // prefetch next tile while computing
            int k0 = kbase + kt + SBK;
            va = *reinterpret_cast<const float2*>(x  + (long)(m0 + alr) * IDIM + k0 + alc);
            vb = *reinterpret_cast<const float4*>(Wm + (long)(n0 + blr) * IDIM + k0 + blc);
        }

#pragma unroll
        for (int k = 0; k < SBK; k++) {
            float a0 = sA[k][ty * 2 + 0];
            float a1 = sA[k][ty * 2 + 1];
            float4 b = *reinterpret_cast<const float4*>(&sB[k][tx * 4]);
            acc[0][0] += a0 * b.x; acc[0][1] += a0 * b.y;
            acc[0][2] += a0 * b.z; acc[0][3] += a0 * b.w;
            acc[1][0] += a1 * b.x; acc[1][1] += a1 * b.y;
            acc[1][2] += a1 * b.z; acc[1][3] += a1 * b.w;
        }
        __syncthreads();
    }

#pragma unroll
    for (int i = 0; i < 2; i++) {
        int m = m0 + ty * 2 + i;
        float4 o = make_float4(acc[i][0], acc[i][1], acc[i][2], acc[i][3]);
        *reinterpret_cast<float4*>(dst + (long)m * NG + n0 + tx * 4) = o;
    }
}

// ---------------------------------------------------------------------------
// K2: fused partial-sum + bias + gate elementwise + per-batch reductions.
// One block (512 thr) per batch.
// ---------------------------------------------------------------------------
__global__ __launch_bounds__(512) void gatered_kernel(
    const float* __restrict__ m_prev,
    const float* __restrict__ n_prev,
    const float* __restrict__ bias,
    float* __restrict__ out)
{
    int b = blockIdx.x;
    int h = threadIdx.x;           // 0..511
    int idx = b * HDIM + h;
    const float* p0 = &g_part[0][(long)b * NG];
    const float* p1 = &g_part[1][(long)b * NG];

    float ig = (p0[h]            + p1[h])            + bias[h];
    float fg = (p0[HDIM + h]     + p1[HDIM + h])     + bias[HDIM + h];
    float og = (p0[2 * HDIM + h] + p1[2 * HDIM + h]) + bias[2 * HDIM + h];
    float qv = (p0[3 * HDIM + h] + p1[3 * HDIM + h]) + bias[3 * HDIM + h];
    float kg = (p0[4 * HDIM + h] + p1[4 * HDIM + h]) + bias[4 * HDIM + h];
    float vg = (p0[5 * HDIM + h] + p1[5 * HDIM + h]) + bias[5 * HDIM + h];

    float mp = m_prev[idx];
    float mt = fmaxf(fg + mp, ig);
    float it = expf(ig - mt);
    float ft = expf(fg + mp - mt);
    float kt = INV_SQRT_H * kg;
    float nt = ft * n_prev[idx] + it * kt;

    out[OUT_M + idx] = mt;
    out[OUT_N + idx] = nt;
    g_q[idx]   = qv;
    g_f[idx]   = ft;
    g_add[idx] = it * vg * kt;
    g_o[idx]   = 1.f / (1.f + expf(-og));

    // block reductions: sq = sum(q), nq = dot(n_t, q)
    float sq = qv;
    float nq = nt * qv;
    for (int s = 16; s; s >>= 1) {
        sq += __shfl_xor_sync(0xffffffffu, sq, s);
        nq += __shfl_xor_sync(0xffffffffu, nq, s);
    }
    __shared__ float s1[16], s2[16];
    int warp = h >> 5, lane = h & 31;
    if (lane == 0) { s1[warp] = sq; s2[warp] = nq; }
    __syncthreads();
    if (warp == 0) {
        sq = (lane < 16) ? s1[lane] : 0.f;
        nq = (lane < 16) ? s2[lane] : 0.f;
        for (int s = 8; s; s >>= 1) {
            sq += __shfl_xor_sync(0xffffffffu, sq, s);
            nq += __shfl_xor_sync(0xffffffffu, nq, s);
        }
        if (lane == 0) {
            g_sumq[b]   = sq;
            g_invden[b] = 1.f / fmaxf(fabsf(nq), 1e-6f);
        }
    }
}

// ---------------------------------------------------------------------------
// K3: THE bandwidth kernel. One warp per C row (2KB): C_t = f*C_prev + add,
// fused Cq = f*dot(C_prev_row, q) + add*sum_q, and h_t written directly.
// ---------------------------------------------------------------------------
__global__ __launch_bounds__(256) void stream_C_kernel(
    const float* __restrict__ Cprev,
    float* __restrict__ out)
{
    __shared__ float sq[HDIM];
    int b  = blockIdx.x >> 6;     // 64 blocks per batch (512 rows / 8)
    int rg = blockIdx.x & 63;
    int tid = threadIdx.x;

    // load biased q[b,:] into smem (float2 x 256 threads)
    const float* qrow = g_q + (long)b * HDIM;
    reinterpret_cast<float2*>(sq)[tid] = reinterpret_cast<const float2*>(qrow)[tid];
    __syncthreads();

    int warp = tid >> 5, lane = tid & 31;
    int i = rg * 8 + warp;
    int bh = b * HDIM + i;
    long rowoff = ((long)b * HDIM + i) * HDIM;

    float fv = g_f[bh];
    float av = g_add[bh];

    const float4* src = reinterpret_cast<const float4*>(Cprev + rowoff);
    float4*       dst = reinterpret_cast<float4*>(out + OUT_C + rowoff);
    const float4* qsv = reinterpret_cast<const float4*>(sq);

    // batch the 4 independent 16B loads first (MLP), then compute+store
    float4 c[4], qv[4];
#pragma unroll
    for (int u = 0; u < 4; u++) c[u] = __ldcs(&src[lane + u * 32]);
#pragma unroll
    for (int u = 0; u < 4; u++) qv[u] = qsv[lane + u * 32];

    float dot = 0.f;
#pragma unroll
    for (int u = 0; u < 4; u++) {
        dot += c[u].x * qv[u].x + c[u].y * qv[u].y
             + c[u].z * qv[u].z + c[u].w * qv[u].w;
        float4 o;
        o.x = fv * c[u].x + av;
        o.y = fv * c[u].y + av;
        o.z = fv * c[u].z + av;
        o.w = fv * c[u].w + av;
        __stcs(&dst[lane + u * 32], o);
    }
    for (int s = 16; s; s >>= 1) dot += __shfl_xor_sync(0xffffffffu, dot, s);
    if (lane == 0) {
        float cq = fv * dot + av * g_sumq[b];
        out[OUT_H + bh] = g_o[bh] * cq * g_invden[b];
    }
}

// ---------------------------------------------------------------------------
// Launch. Inputs (metadata order): x, h_prev, C_prev, m_prev, n_prev, W, b
// ---------------------------------------------------------------------------
extern "C" void kernel_launch(void* const* d_in, const int* in_sizes, int n_in,
                              void* d_out, int out_size)
{
    const float* x      = (const float*)d_in[0];
    // d_in[1] = h_prev (unused by reference)
    const float* C_prev = (const float*)d_in[2];
    const float* m_prev = (const float*)d_in[3];
    const float* n_prev = (const float*)d_in[4];
    const float* W      = (const float*)d_in[5];
    const float* bias   = (const float*)d_in[6];
    float* out = (float*)d_out;

    // K1: split-K fp32 GEMM (384 blocks x 256 threads)
    dim3 ggrid(NG / SBN, BATCH / SBM, 2);
    gemm_splitk_kernel<<<ggrid, 256>>>(x, W);

    // K2: fused split-K sum + bias + gate elementwise + reductions
    gatered_kernel<<<BATCH, 512>>>(m_prev, n_prev, bias, out);

    // K3: C stream + fused Cq + h_t
    stream_C_kernel<<<BATCH * (HDIM / 8), 256>>>(C_prev, out);
}